// round 5
// baseline (speedup 1.0000x reference)
#include <cuda_runtime.h>
#include <cuda_bf16.h>
#include <math.h>

// Problem constants
#define Bv   4
#define Sv   1024
#define Dv   1024
#define Vv   32000
#define Lv   2
#define Hv   8
#define QSv  1024
#define BSv  (Bv*Sv)        // 4096 token rows
#define HQ   (Hv*QSv)       // 8192 concat width
#define FFv  (4*Dv)         // 4096 ffn hidden

// ---------------------------------------------------------------------------
// Scratch (static device globals; allocation in kernel_launch is forbidden)
// ---------------------------------------------------------------------------
__device__ double g_invfreq[Dv/2];                //  4 KB  10000^(-2i/D)
__device__ float g_pos[(size_t)Sv*Dv];            //   4 MB  positional encoding
__device__ float g_h  [(size_t)BSv*Dv];           //  16 MB  hidden state
__device__ float g_q  [(size_t)Hv*BSv*QSv];       // 128 MB  Q  [H, B*S, QS]
__device__ float g_k  [(size_t)Hv*BSv*QSv];       // 128 MB  K
__device__ float g_v  [(size_t)Hv*BSv*QSv];       // 128 MB  V
__device__ float g_sc [(size_t)Hv*Bv*Sv*Sv];      // 128 MB  scores/attn [H,B,S,S]
__device__ float g_oc [(size_t)BSv*HQ];           // 128 MB  concat attn out [B*S, H*QS]
__device__ float g_a  [(size_t)BSv*Dv];           //  16 MB  post-attn proj / ffn out
__device__ float g_fin[(size_t)BSv*Dv];           //  16 MB  ln1 output (ffn residual)
__device__ float g_mid[(size_t)BSv*FFv];          //  64 MB  ffn hidden

// ---------------------------------------------------------------------------
// Batched SGEMM: C[z] = A[z] @ (B[z] or B[z]^T) + bias, optional ReLU.
// Grid: (M/128, N/128, z) — M-tiles on the FAST axis so one wave spans all
// row-blocks of a few col-tiles: B col-slices are read once and shared by
// all row CTAs (L2), A stays L2-resident. Critical for the 128 MB LM head.
// z-offsets: with z1 = z/zdiv, z2 = z%zdiv, pointer += z1*s?1 + z2*s?2.
// Tile 128x128x16, 256 threads, 8x8 per thread, double-buffered smem,
// float4 global loads + LDS.128 fragment reads. All dims divisible by tile.
// causal: 0 = none; 1 = skip tiles with col0 > row0 (fully-masked score
//         tile); 2 = clamp K to row0+128 (attn rows are 0 past diagonal).
// ---------------------------------------------------------------------------
template<bool TRANSB>
__global__ __launch_bounds__(256)
void gemm_kernel(const float* __restrict__ A, int lda, long long sA1, long long sA2,
                 const float* __restrict__ Bp, int ldb, long long sB1, long long sB2,
                 float* __restrict__ C, int ldc, long long sC1, long long sC2,
                 const float* __restrict__ bias, long long sb1,
                 int M, int N, int K, int zdiv, int relu, int causal)
{
    const int row0 = blockIdx.x * 128;            // fast axis = rows
    const int col0 = blockIdx.y * 128;
    if (causal == 1 && col0 > row0) return;       // fully-masked score tile
    if (causal == 2) K = min(K, row0 + 128);      // attn rows are 0 past diag

    const int z  = blockIdx.z;
    const int z1 = z / zdiv;
    const int z2 = z % zdiv;
    A  += z1 * sA1 + z2 * sA2;
    Bp += z1 * sB1 + z2 * sB2;
    C  += z1 * sC1 + z2 * sC2;
    if (bias) bias += z1 * sb1;

    __shared__ float As[2][16][132];
    __shared__ float Bs[2][16][132];

    const int tid = threadIdx.x;          // 0..255
    const int tx  = tid & 15;             // 16 col groups
    const int ty  = tid >> 4;             // 16 row groups

    // Per-thread load slots (2 float4 for A, 2 for B)
    const int e0 = tid, e1 = tid + 256;
    // A tile: 128 rows x 16 k, vector along k
    const int rA0 = e0 >> 2, cA0 = (e0 & 3) * 4;
    const int rA1 = e1 >> 2, cA1 = (e1 & 3) * 4;
    // B tile (TRANSB): 128 n-rows x 16 k, vector along k
    const int nT0 = e0 >> 2, cT0 = (e0 & 3) * 4;
    const int nT1 = e1 >> 2, cT1 = (e1 & 3) * 4;
    // B tile (no trans): 16 k-rows x 128 n, vector along n
    const int cN0 = e0 >> 5, nN0 = (e0 & 31) * 4;
    const int cN1 = e1 >> 5, nN1 = (e1 & 31) * 4;

    auto loadA = [&](int k0, float4& a0, float4& a1) {
        a0 = *(const float4*)&A[(long long)(row0 + rA0) * lda + (k0 + cA0)];
        a1 = *(const float4*)&A[(long long)(row0 + rA1) * lda + (k0 + cA1)];
    };
    auto loadB = [&](int k0, float4& b0, float4& b1) {
        if (TRANSB) {
            b0 = *(const float4*)&Bp[(long long)(col0 + nT0) * ldb + (k0 + cT0)];
            b1 = *(const float4*)&Bp[(long long)(col0 + nT1) * ldb + (k0 + cT1)];
        } else {
            b0 = *(const float4*)&Bp[(long long)(k0 + cN0) * ldb + (col0 + nN0)];
            b1 = *(const float4*)&Bp[(long long)(k0 + cN1) * ldb + (col0 + nN1)];
        }
    };
    auto storeA = [&](int buf, float4 a0, float4 a1) {
        As[buf][cA0 + 0][rA0] = a0.x; As[buf][cA0 + 1][rA0] = a0.y;
        As[buf][cA0 + 2][rA0] = a0.z; As[buf][cA0 + 3][rA0] = a0.w;
        As[buf][cA1 + 0][rA1] = a1.x; As[buf][cA1 + 1][rA1] = a1.y;
        As[buf][cA1 + 2][rA1] = a1.z; As[buf][cA1 + 3][rA1] = a1.w;
    };
    auto storeB = [&](int buf, float4 b0, float4 b1) {
        if (TRANSB) {
            Bs[buf][cT0 + 0][nT0] = b0.x; Bs[buf][cT0 + 1][nT0] = b0.y;
            Bs[buf][cT0 + 2][nT0] = b0.z; Bs[buf][cT0 + 3][nT0] = b0.w;
            Bs[buf][cT1 + 0][nT1] = b1.x; Bs[buf][cT1 + 1][nT1] = b1.y;
            Bs[buf][cT1 + 2][nT1] = b1.z; Bs[buf][cT1 + 3][nT1] = b1.w;
        } else {
            *(float4*)&Bs[buf][cN0][nN0] = b0;
            *(float4*)&Bs[buf][cN1][nN1] = b1;
        }
    };

    float acc[8][8];
    #pragma unroll
    for (int i = 0; i < 8; i++)
        #pragma unroll
        for (int j = 0; j < 8; j++) acc[i][j] = 0.f;

    const int nt = K / 16;
    float4 va0, va1, vb0, vb1;
    loadA(0, va0, va1);
    loadB(0, vb0, vb1);
    storeA(0, va0, va1);
    storeB(0, vb0, vb1);
    __syncthreads();

    int buf = 0;
    for (int t = 0; t < nt; t++) {
        const bool has_next = (t + 1 < nt);
        if (has_next) {
            loadA((t + 1) * 16, va0, va1);
            loadB((t + 1) * 16, vb0, vb1);
        }

        #pragma unroll
        for (int kk = 0; kk < 16; kk++) {
            float4 a0 = *(const float4*)&As[buf][kk][ty * 8];
            float4 a1 = *(const float4*)&As[buf][kk][ty * 8 + 4];
            float4 b0 = *(const float4*)&Bs[buf][kk][tx * 8];
            float4 b1 = *(const float4*)&Bs[buf][kk][tx * 8 + 4];
            float ra[8] = {a0.x, a0.y, a0.z, a0.w, a1.x, a1.y, a1.z, a1.w};
            float rb[8] = {b0.x, b0.y, b0.z, b0.w, b1.x, b1.y, b1.z, b1.w};
            #pragma unroll
            for (int i = 0; i < 8; i++)
                #pragma unroll
                for (int j = 0; j < 8; j++)
                    acc[i][j] += ra[i] * rb[j];
        }

        if (has_next) {
            storeA(buf ^ 1, va0, va1);
            storeB(buf ^ 1, vb0, vb1);
            __syncthreads();
            buf ^= 1;
        }
    }

    // Epilogue: bias + optional relu, float4 stores
    #pragma unroll
    for (int i = 0; i < 8; i++) {
        long long r = row0 + ty * 8 + i;
        float* crow = C + r * ldc + (col0 + tx * 8);
        float o[8];
        #pragma unroll
        for (int j = 0; j < 8; j++) {
            float val = acc[i][j];
            if (bias) val += bias[col0 + tx * 8 + j];
            if (relu) val = fmaxf(val, 0.f);
            o[j] = val;
        }
        *(float4*)&crow[0] = make_float4(o[0], o[1], o[2], o[3]);
        *(float4*)&crow[4] = make_float4(o[4], o[5], o[6], o[7]);
    }
}

// ---------------------------------------------------------------------------
// Positional encoding. inv_freq precomputed in double (512 cheap fp64 exp);
// per element: one DMUL (exact angle) + float sincos. Angle conversion error
// <= 1023 * 2^-24 ~ 6e-5 rad -> well inside the 1e-3 output gate.
// ---------------------------------------------------------------------------
__global__ void freq_kernel()
{
    int i = threadIdx.x + blockIdx.x * 256;
    if (i < Dv / 2)
        g_invfreq[i] = exp(-((double)(2 * i) / (double)Dv) * log(10000.0));
}

__global__ void posenc_kernel(float* __restrict__ pos)
{
    int idx = blockIdx.x * 256 + threadIdx.x;   // S*D = 1M
    int d = idx & (Dv - 1);
    int s = idx >> 10;
    int i = d >> 1;
    float ang = (float)((double)s * g_invfreq[i]);
    pos[idx] = (d & 1) ? cosf(ang) : sinf(ang);
}

// h[b,s,d] = emb[x[b,s], d] + posenc[s, d]
__global__ void embed_kernel(const int* __restrict__ x, const float* __restrict__ emb,
                             const float* __restrict__ pos, float* __restrict__ h)
{
    long long idx = (long long)blockIdx.x * 256 + threadIdx.x;  // B*S*D = 4M
    int d = (int)(idx & (Dv - 1));
    long long bs = idx >> 10;
    int s = (int)(bs & (Sv - 1));
    int tok = x[bs];
    h[idx] = emb[(long long)tok * Dv + d] + pos[s * Dv + d];
}

// ---------------------------------------------------------------------------
// Row softmax with causal mask (+ 1/sqrt(D) scale), in-place on [.., S, S].
// Reads only k <= q (mask ignores memory); writes only k < tile_end, the
// region the downstream AV GEMM (causal=2) actually reads. Entries in
// (q, tile_end) are exactly 0 (exp underflow), matching the reference.
// ---------------------------------------------------------------------------
__global__ void softmax_kernel(float* __restrict__ sc)
{
    __shared__ float red[8];
    long long row = blockIdx.x;               // H*B*S rows
    float* p = sc + row * Sv;
    int q = (int)(row & (Sv - 1));
    int tile_end = ((q >> 7) + 1) << 7;       // 128-aligned end of diag tile
    int tid = threadIdx.x;                    // 256

    float v[4];
    float mx = -3.0e38f;
    #pragma unroll
    for (int i = 0; i < 4; i++) {
        int kk = tid + i * 256;
        float s = (kk > q) ? -1e9f : p[kk] * 0.03125f;   // 1/sqrt(1024)
        v[i] = s;
        mx = fmaxf(mx, s);
    }
    #pragma unroll
    for (int o = 16; o; o >>= 1) mx = fmaxf(mx, __shfl_xor_sync(0xffffffffu, mx, o));
    if ((tid & 31) == 0) red[tid >> 5] = mx;
    __syncthreads();
    mx = red[0];
    #pragma unroll
    for (int w = 1; w < 8; w++) mx = fmaxf(mx, red[w]);

    float sum = 0.f;
    #pragma unroll
    for (int i = 0; i < 4; i++) { v[i] = expf(v[i] - mx); sum += v[i]; }
    #pragma unroll
    for (int o = 16; o; o >>= 1) sum += __shfl_xor_sync(0xffffffffu, sum, o);
    __syncthreads();
    if ((tid & 31) == 0) red[tid >> 5] = sum;
    __syncthreads();
    sum = 0.f;
    #pragma unroll
    for (int w = 0; w < 8; w++) sum += red[w];

    float inv = 1.f / sum;
    #pragma unroll
    for (int i = 0; i < 4; i++) {
        int kk = tid + i * 256;
        if (kk < tile_end) p[kk] = v[i] * inv;
    }
}

// ---------------------------------------------------------------------------
// out = LayerNorm(xa + xb) * g + b  (rows of D=1024)
// ---------------------------------------------------------------------------
__global__ void add_ln_kernel(const float* __restrict__ xa, const float* __restrict__ xb,
                              const float* __restrict__ g, const float* __restrict__ bt,
                              float* __restrict__ out)
{
    __shared__ float red[8];
    long long row = blockIdx.x;
    const float* pa = xa + row * Dv;
    const float* pb = xb + row * Dv;
    float* po = out + row * Dv;
    int tid = threadIdx.x;

    float v[4];
    float s = 0.f;
    #pragma unroll
    for (int i = 0; i < 4; i++) {
        int c = tid + i * 256;
        v[i] = pa[c] + pb[c];
        s += v[i];
    }
    #pragma unroll
    for (int o = 16; o; o >>= 1) s += __shfl_xor_sync(0xffffffffu, s, o);
    if ((tid & 31) == 0) red[tid >> 5] = s;
    __syncthreads();
    s = 0.f;
    #pragma unroll
    for (int w = 0; w < 8; w++) s += red[w];
    float mu = s * (1.f / Dv);

    float sq = 0.f;
    #pragma unroll
    for (int i = 0; i < 4; i++) { float d = v[i] - mu; sq += d * d; }
    #pragma unroll
    for (int o = 16; o; o >>= 1) sq += __shfl_xor_sync(0xffffffffu, sq, o);
    __syncthreads();
    if ((tid & 31) == 0) red[tid >> 5] = sq;
    __syncthreads();
    sq = 0.f;
    #pragma unroll
    for (int w = 0; w < 8; w++) sq += red[w];
    float inv = rsqrtf(sq * (1.f / Dv) + 1e-5f);

    #pragma unroll
    for (int i = 0; i < 4; i++) {
        int c = tid + i * 256;
        po[c] = (v[i] - mu) * inv * g[c] + bt[c];
    }
}

// ---------------------------------------------------------------------------
// Host orchestration
// ---------------------------------------------------------------------------
extern "C" void kernel_launch(void* const* d_in, const int* in_sizes, int n_in,
                              void* d_out, int out_size)
{
    const int*   x    = (const int*)  d_in[0];
    const float* emb  = (const float*)d_in[1];
    const float* wq   = (const float*)d_in[2];
    const float* bq   = (const float*)d_in[3];
    const float* wk   = (const float*)d_in[4];
    const float* bk   = (const float*)d_in[5];
    const float* wv   = (const float*)d_in[6];
    const float* bv   = (const float*)d_in[7];
    const float* wr   = (const float*)d_in[8];
    const float* br   = (const float*)d_in[9];
    const float* ln1g = (const float*)d_in[10];
    const float* ln1b = (const float*)d_in[11];
    const float* w1   = (const float*)d_in[12];
    const float* b1   = (const float*)d_in[13];
    const float* w2   = (const float*)d_in[14];
    const float* b2   = (const float*)d_in[15];
    const float* ln2g = (const float*)d_in[16];
    const float* ln2b = (const float*)d_in[17];
    const float* wf   = (const float*)d_in[18];
    const float* bf   = (const float*)d_in[19];
    float* out = (float*)d_out;

    float *pos, *h, *q, *k, *v, *sc, *oc, *a, *fin, *mid;
    cudaGetSymbolAddress((void**)&pos, g_pos);
    cudaGetSymbolAddress((void**)&h,   g_h);
    cudaGetSymbolAddress((void**)&q,   g_q);
    cudaGetSymbolAddress((void**)&k,   g_k);
    cudaGetSymbolAddress((void**)&v,   g_v);
    cudaGetSymbolAddress((void**)&sc,  g_sc);
    cudaGetSymbolAddress((void**)&oc,  g_oc);
    cudaGetSymbolAddress((void**)&a,   g_a);
    cudaGetSymbolAddress((void**)&fin, g_fin);
    cudaGetSymbolAddress((void**)&mid, g_mid);

    freq_kernel<<<2, 256>>>();
    posenc_kernel<<<(Sv * Dv) / 256, 256>>>(pos);
    embed_kernel<<<(BSv * Dv) / 256, 256>>>(x, emb, pos, h);

    const long long HS  = (long long)Sv * QSv;       // per-(b,h) Q/K/V block
    const long long HBS = (long long)BSv * QSv;      // per-head Q/K/V block
    const long long SS  = (long long)Sv * Sv;

    for (int l = 0; l < Lv; l++) {
        const float* wq_l = wq + (size_t)l * Hv * Dv * QSv;
        const float* wk_l = wk + (size_t)l * Hv * Dv * QSv;
        const float* wv_l = wv + (size_t)l * Hv * Dv * QSv;
        const float* bq_l = bq + (size_t)l * Hv * QSv;
        const float* bk_l = bk + (size_t)l * Hv * QSv;
        const float* bv_l = bv + (size_t)l * Hv * QSv;
        const float* wr_l = wr + (size_t)l * HQ * Dv;
        const float* br_l = br + (size_t)l * Dv;
        const float* w1_l = w1 + (size_t)l * Dv * FFv;
        const float* b1_l = b1 + (size_t)l * FFv;
        const float* w2_l = w2 + (size_t)l * FFv * Dv;
        const float* b2_l = b2 + (size_t)l * Dv;

        // Q/K/V projections: per-head GEMM [B*S, D] @ [D, QS], z over heads
        // Grid = (M-tiles, N-tiles, z): rows fast for L2 weight reuse.
        gemm_kernel<false><<<dim3(BSv/128, QSv/128, Hv), 256>>>(
            h, Dv, 0, 0, wq_l, QSv, (long long)Dv*QSv, 0,
            q, QSv, HBS, 0, bq_l, QSv, BSv, QSv, Dv, 1, 0, 0);
        gemm_kernel<false><<<dim3(BSv/128, QSv/128, Hv), 256>>>(
            h, Dv, 0, 0, wk_l, QSv, (long long)Dv*QSv, 0,
            k, QSv, HBS, 0, bk_l, QSv, BSv, QSv, Dv, 1, 0, 0);
        gemm_kernel<false><<<dim3(BSv/128, QSv/128, Hv), 256>>>(
            h, Dv, 0, 0, wv_l, QSv, (long long)Dv*QSv, 0,
            v, QSv, HBS, 0, bv_l, QSv, BSv, QSv, Dv, 1, 0, 0);

        // scores = Q @ K^T per (h,b), z = h*B + b; upper-triangle tiles skipped
        gemm_kernel<true><<<dim3(Sv/128, Sv/128, Hv*Bv), 256>>>(
            q, QSv, HS, 0, k, QSv, HS, 0,
            sc, Sv, SS, 0, nullptr, 0, Sv, Sv, QSv, 1, 0, 1);

        // causal softmax (scale applied inside; masked entries ignore memory)
        softmax_kernel<<<Hv * Bv * Sv, 256>>>(sc);

        // o = attn @ V (K clamped to diagonal), concat layout [B*S, H*QS]
        gemm_kernel<false><<<dim3(Sv/128, QSv/128, Hv*Bv), 256>>>(
            sc, Sv, (long long)Bv*SS, SS,
            v, QSv, HBS, HS,
            oc, HQ, QSv, (long long)Sv*HQ,
            nullptr, 0, Sv, QSv, Sv, Bv, 0, 2);

        // reducing layer: a = o_cat @ wr + br   [4096, 8192] @ [8192, 1024]
        gemm_kernel<false><<<dim3(BSv/128, Dv/128, 1), 256>>>(
            oc, HQ, 0, 0, wr_l, Dv, 0, 0,
            a, Dv, 0, 0, br_l, 0, BSv, Dv, HQ, 1, 0, 0);

        // ff_in = LN(a + h)
        add_ln_kernel<<<BSv, 256>>>(a, h, ln1g + (size_t)l*Dv, ln1b + (size_t)l*Dv, fin);

        // FFN
        gemm_kernel<false><<<dim3(BSv/128, FFv/128, 1), 256>>>(
            fin, Dv, 0, 0, w1_l, FFv, 0, 0,
            mid, FFv, 0, 0, b1_l, 0, BSv, FFv, Dv, 1, 1, 0);
        gemm_kernel<false><<<dim3(BSv/128, Dv/128, 1), 256>>>(
            mid, FFv, 0, 0, w2_l, Dv, 0, 0,
            a, Dv, 0, 0, b2_l, 0, BSv, Dv, FFv, 1, 0, 0);

        // h = LN(ff + ff_in)
        add_ln_kernel<<<BSv, 256>>>(a, fin, ln2g + (size_t)l*Dv, ln2b + (size_t)l*Dv, h);
    }

    // logits = h @ wf + bf   [4096, 1024] @ [1024, 32000]
    // Rows on fast axis: wf (128 MB) read once from DRAM, h L2-resident.
    gemm_kernel<false><<<dim3(BSv/128, Vv/128, 1), 256>>>(
        h, Dv, 0, 0, wf, Vv, 0, 0,
        out, Vv, 0, 0, bf, 0, BSv, Vv, Dv, 1, 0, 0);
}

// round 8
// speedup vs baseline: 4.9069x; 4.9069x over previous
#include <cuda_runtime.h>
#include <cuda_bf16.h>
#include <math.h>
#include <stdint.h>

// Problem constants
#define Bv   4
#define Sv   1024
#define Dv   1024
#define Vv   32000
#define Lv   2
#define Hv   8
#define QSv  1024
#define BSv  (Bv*Sv)        // 4096 token rows
#define HQ   (Hv*QSv)       // 8192 concat width
#define FFv  (4*Dv)         // 4096 ffn hidden

// ---------------------------------------------------------------------------
// Scratch (static device globals; allocation in kernel_launch is forbidden)
// ---------------------------------------------------------------------------
__device__ double g_invfreq[Dv/2];                //  4 KB  10000^(-2i/D)
__device__ float g_pos[(size_t)Sv*Dv];            //   4 MB  positional encoding
__device__ float g_h  [(size_t)BSv*Dv];           //  16 MB  hidden state
__device__ float g_q  [(size_t)Hv*BSv*QSv];       // 128 MB  Q  [H, B*S, QS]
__device__ float g_k  [(size_t)Hv*BSv*QSv];       // 128 MB  K
__device__ float g_v  [(size_t)Hv*BSv*QSv];       // 128 MB  V
__device__ float g_sc [(size_t)Hv*Bv*Sv*Sv];      // 128 MB  scores/attn [H,B,S,S]
__device__ float g_oc [(size_t)BSv*HQ];           // 128 MB  concat attn out [B*S, H*QS]
__device__ float g_a  [(size_t)BSv*Dv];           //  16 MB  post-attn proj / ffn out
__device__ float g_fin[(size_t)BSv*Dv];           //  16 MB  ln1 output (ffn residual)
__device__ float g_mid[(size_t)BSv*FFv];          //  64 MB  ffn hidden

// ---------------------------------------------------------------------------
// tf32 helpers
// ---------------------------------------------------------------------------
__device__ __forceinline__ uint32_t f2tf(float f)
{
    uint32_t u;
    asm("cvt.rna.tf32.f32 %0, %1;" : "=r"(u) : "f"(f));
    return u;
}

__device__ __forceinline__ void mma_tf32(float c[4], const uint32_t a[4], const uint32_t b[2])
{
    asm volatile(
        "mma.sync.aligned.m16n8k8.row.col.f32.tf32.tf32.f32 "
        "{%0,%1,%2,%3}, {%4,%5,%6,%7}, {%8,%9}, {%0,%1,%2,%3};"
        : "+f"(c[0]), "+f"(c[1]), "+f"(c[2]), "+f"(c[3])
        : "r"(a[0]), "r"(a[1]), "r"(a[2]), "r"(a[3]), "r"(b[0]), "r"(b[1]));
}

// ---------------------------------------------------------------------------
// Batched tf32 tensor-core GEMM: C[z] = A[z] @ (B[z] or B[z]^T) + bias, relu.
// Grid: (M/128, N/128, z) — M-tiles on the FAST axis for L2 weight reuse.
// CTA tile 128x128, K-tile 32, 8 warps as 2(M) x 4(N) -> 64x32 warp tiles,
// m16n8k8 tf32 atoms (4x4 per warp), fp32 accumulate. Single smem buffer with
// register-staged global prefetch. Smem pads: As stride 36 (frag bank =
// 4*gid+tig, conflict-free), Bs stride 136 (frag bank = 8*tig+gid, c-free).
// causal: 0 none; 1 skip tiles col0 > row0; 2 clamp K to row0+128.
// All M/N divisible by 128, K divisible by 32.
// ---------------------------------------------------------------------------
template<bool TRANSB>
__global__ __launch_bounds__(256)
void gemm_kernel(const float* __restrict__ A, int lda, long long sA1, long long sA2,
                 const float* __restrict__ Bp, int ldb, long long sB1, long long sB2,
                 float* __restrict__ C, int ldc, long long sC1, long long sC2,
                 const float* __restrict__ bias, long long sb1,
                 int M, int N, int K, int zdiv, int relu, int causal)
{
    const int row0 = blockIdx.x * 128;            // fast axis = rows
    const int col0 = blockIdx.y * 128;
    if (causal == 1 && col0 > row0) return;       // fully-masked score tile
    if (causal == 2) K = min(K, row0 + 128);      // attn rows are 0 past diag

    const int z  = blockIdx.z;
    const int z1 = z / zdiv;
    const int z2 = z % zdiv;
    A  += z1 * sA1 + z2 * sA2;
    Bp += z1 * sB1 + z2 * sB2;
    C  += z1 * sC1 + z2 * sC2;
    if (bias) bias += z1 * sb1;

    __shared__ uint32_t As[128][36];   // [m][k], padded
    __shared__ uint32_t Bs[32][136];   // [k][n], padded

    const int tid  = threadIdx.x;      // 0..255
    const int warp = tid >> 5;
    const int lane = tid & 31;
    const int gid  = lane >> 2;        // 0..7
    const int tig  = lane & 3;         // 0..3
    const int mW   = (warp & 1) * 64;  // warp M offset in tile
    const int nW   = (warp >> 1) * 32; // warp N offset in tile

    // ---- staging register load maps (4 float4 A + 4 float4 B per thread) ---
    // A: f4 = tid + i*256 -> m = f4>>3 (0..127), kc = (f4&7)*4
    // B no-trans: k = f4>>5 (0..31), n = (f4&31)*4
    // B trans: wIdx = f4>>5; kc = (wIdx&7)*4; n = (wIdx>>3)*32 + (f4&31)
    int amr[4], akc[4], bk[4], bn[4];
    #pragma unroll
    for (int i = 0; i < 4; i++) {
        int f4 = tid + i * 256;
        amr[i] = f4 >> 3;
        akc[i] = (f4 & 7) * 4;
        if (TRANSB) {
            int w = f4 >> 5;
            bk[i] = (w & 7) * 4;            // k start of the 4 elems
            bn[i] = (w >> 3) * 32 + (f4 & 31);
        } else {
            bk[i] = f4 >> 5;
            bn[i] = (f4 & 31) * 4;
        }
    }

    float4 sa[4], sb[4];
    auto gload = [&](int k0) {
        #pragma unroll
        for (int i = 0; i < 4; i++)
            sa[i] = *(const float4*)&A[(long long)(row0 + amr[i]) * lda + (k0 + akc[i])];
        #pragma unroll
        for (int i = 0; i < 4; i++) {
            if (TRANSB)
                sb[i] = *(const float4*)&Bp[(long long)(col0 + bn[i]) * ldb + (k0 + bk[i])];
            else
                sb[i] = *(const float4*)&Bp[(long long)(k0 + bk[i]) * ldb + (col0 + bn[i])];
        }
    };
    auto sstore = [&]() {
        #pragma unroll
        for (int i = 0; i < 4; i++) {
            As[amr[i]][akc[i] + 0] = f2tf(sa[i].x);
            As[amr[i]][akc[i] + 1] = f2tf(sa[i].y);
            As[amr[i]][akc[i] + 2] = f2tf(sa[i].z);
            As[amr[i]][akc[i] + 3] = f2tf(sa[i].w);
        }
        #pragma unroll
        for (int i = 0; i < 4; i++) {
            if (TRANSB) {
                // 4 elems along k, scatter-transpose; banks distinct (n fast)
                Bs[bk[i] + 0][bn[i]] = f2tf(sb[i].x);
                Bs[bk[i] + 1][bn[i]] = f2tf(sb[i].y);
                Bs[bk[i] + 2][bn[i]] = f2tf(sb[i].z);
                Bs[bk[i] + 3][bn[i]] = f2tf(sb[i].w);
            } else {
                Bs[bk[i]][bn[i] + 0] = f2tf(sb[i].x);
                Bs[bk[i]][bn[i] + 1] = f2tf(sb[i].y);
                Bs[bk[i]][bn[i] + 2] = f2tf(sb[i].z);
                Bs[bk[i]][bn[i] + 3] = f2tf(sb[i].w);
            }
        }
    };

    float acc[4][4][4];                 // [ma][na][reg]
    #pragma unroll
    for (int i = 0; i < 4; i++)
        #pragma unroll
        for (int j = 0; j < 4; j++)
            #pragma unroll
            for (int r = 0; r < 4; r++) acc[i][j][r] = 0.f;

    const int nt = K / 32;
    gload(0);
    for (int t = 0; t < nt; t++) {
        sstore();
        __syncthreads();
        if (t + 1 < nt) gload((t + 1) * 32);

        #pragma unroll
        for (int ka = 0; ka < 4; ka++) {
            uint32_t af[4][4];
            #pragma unroll
            for (int ma = 0; ma < 4; ma++) {
                int r = mW + ma * 16 + gid;
                int c = ka * 8 + tig;
                af[ma][0] = As[r][c];
                af[ma][1] = As[r + 8][c];
                af[ma][2] = As[r][c + 4];
                af[ma][3] = As[r + 8][c + 4];
            }
            uint32_t bf[4][2];
            #pragma unroll
            for (int na = 0; na < 4; na++) {
                int c = nW + na * 8 + gid;
                bf[na][0] = Bs[ka * 8 + tig][c];
                bf[na][1] = Bs[ka * 8 + tig + 4][c];
            }
            #pragma unroll
            for (int ma = 0; ma < 4; ma++)
                #pragma unroll
                for (int na = 0; na < 4; na++)
                    mma_tf32(acc[ma][na], af[ma], bf[na]);
        }
        __syncthreads();
    }

    // Epilogue: bias + optional relu, float2 stores (coalesced 32B runs/row)
    #pragma unroll
    for (int ma = 0; ma < 4; ma++) {
        #pragma unroll
        for (int na = 0; na < 4; na++) {
            int cc = col0 + nW + na * 8 + 2 * tig;
            float b0 = bias ? bias[cc] : 0.f;
            float b1 = bias ? bias[cc + 1] : 0.f;
            long long r0 = row0 + mW + ma * 16 + gid;
            long long r1 = r0 + 8;
            float v0 = acc[ma][na][0] + b0;
            float v1 = acc[ma][na][1] + b1;
            float v2 = acc[ma][na][2] + b0;
            float v3 = acc[ma][na][3] + b1;
            if (relu) {
                v0 = fmaxf(v0, 0.f); v1 = fmaxf(v1, 0.f);
                v2 = fmaxf(v2, 0.f); v3 = fmaxf(v3, 0.f);
            }
            *(float2*)&C[r0 * ldc + cc] = make_float2(v0, v1);
            *(float2*)&C[r1 * ldc + cc] = make_float2(v2, v3);
        }
    }
}

// ---------------------------------------------------------------------------
// Positional encoding. inv_freq precomputed in double (512 cheap fp64 exp);
// per element: one DMUL (exact angle) + float sincos.
// ---------------------------------------------------------------------------
__global__ void freq_kernel()
{
    int i = threadIdx.x + blockIdx.x * 256;
    if (i < Dv / 2)
        g_invfreq[i] = exp(-((double)(2 * i) / (double)Dv) * log(10000.0));
}

__global__ void posenc_kernel(float* __restrict__ pos)
{
    int idx = blockIdx.x * 256 + threadIdx.x;   // S*D = 1M
    int d = idx & (Dv - 1);
    int s = idx >> 10;
    int i = d >> 1;
    float ang = (float)((double)s * g_invfreq[i]);
    pos[idx] = (d & 1) ? cosf(ang) : sinf(ang);
}

// h[b,s,d] = emb[x[b,s], d] + posenc[s, d]
__global__ void embed_kernel(const int* __restrict__ x, const float* __restrict__ emb,
                             const float* __restrict__ pos, float* __restrict__ h)
{
    long long idx = (long long)blockIdx.x * 256 + threadIdx.x;  // B*S*D = 4M
    int d = (int)(idx & (Dv - 1));
    long long bs = idx >> 10;
    int s = (int)(bs & (Sv - 1));
    int tok = x[bs];
    h[idx] = emb[(long long)tok * Dv + d] + pos[s * Dv + d];
}

// ---------------------------------------------------------------------------
// Row softmax with causal mask (+ 1/sqrt(D) scale), in-place on [.., S, S].
// Reads only k <= q; writes only k < tile_end (the region AV reads).
// ---------------------------------------------------------------------------
__global__ void softmax_kernel(float* __restrict__ sc)
{
    __shared__ float red[8];
    long long row = blockIdx.x;               // H*B*S rows
    float* p = sc + row * Sv;
    int q = (int)(row & (Sv - 1));
    int tile_end = ((q >> 7) + 1) << 7;       // 128-aligned end of diag tile
    int tid = threadIdx.x;                    // 256

    float v[4];
    float mx = -3.0e38f;
    #pragma unroll
    for (int i = 0; i < 4; i++) {
        int kk = tid + i * 256;
        float s = (kk > q) ? -1e9f : p[kk] * 0.03125f;   // 1/sqrt(1024)
        v[i] = s;
        mx = fmaxf(mx, s);
    }
    #pragma unroll
    for (int o = 16; o; o >>= 1) mx = fmaxf(mx, __shfl_xor_sync(0xffffffffu, mx, o));
    if ((tid & 31) == 0) red[tid >> 5] = mx;
    __syncthreads();
    mx = red[0];
    #pragma unroll
    for (int w = 1; w < 8; w++) mx = fmaxf(mx, red[w]);

    float sum = 0.f;
    #pragma unroll
    for (int i = 0; i < 4; i++) { v[i] = expf(v[i] - mx); sum += v[i]; }
    #pragma unroll
    for (int o = 16; o; o >>= 1) sum += __shfl_xor_sync(0xffffffffu, sum, o);
    __syncthreads();
    if ((tid & 31) == 0) red[tid >> 5] = sum;
    __syncthreads();
    sum = 0.f;
    #pragma unroll
    for (int w = 0; w < 8; w++) sum += red[w];

    float inv = 1.f / sum;
    #pragma unroll
    for (int i = 0; i < 4; i++) {
        int kk = tid + i * 256;
        if (kk < tile_end) p[kk] = v[i] * inv;
    }
}

// ---------------------------------------------------------------------------
// out = LayerNorm(xa + xb) * g + b  (rows of D=1024)
// ---------------------------------------------------------------------------
__global__ void add_ln_kernel(const float* __restrict__ xa, const float* __restrict__ xb,
                              const float* __restrict__ g, const float* __restrict__ bt,
                              float* __restrict__ out)
{
    __shared__ float red[8];
    long long row = blockIdx.x;
    const float* pa = xa + row * Dv;
    const float* pb = xb + row * Dv;
    float* po = out + row * Dv;
    int tid = threadIdx.x;

    float v[4];
    float s = 0.f;
    #pragma unroll
    for (int i = 0; i < 4; i++) {
        int c = tid + i * 256;
        v[i] = pa[c] + pb[c];
        s += v[i];
    }
    #pragma unroll
    for (int o = 16; o; o >>= 1) s += __shfl_xor_sync(0xffffffffu, s, o);
    if ((tid & 31) == 0) red[tid >> 5] = s;
    __syncthreads();
    s = 0.f;
    #pragma unroll
    for (int w = 0; w < 8; w++) s += red[w];
    float mu = s * (1.f / Dv);

    float sq = 0.f;
    #pragma unroll
    for (int i = 0; i < 4; i++) { float d = v[i] - mu; sq += d * d; }
    #pragma unroll
    for (int o = 16; o; o >>= 1) sq += __shfl_xor_sync(0xffffffffu, sq, o);
    __syncthreads();
    if ((tid & 31) == 0) red[tid >> 5] = sq;
    __syncthreads();
    sq = 0.f;
    #pragma unroll
    for (int w = 0; w < 8; w++) sq += red[w];
    float inv = rsqrtf(sq * (1.f / Dv) + 1e-5f);

    #pragma unroll
    for (int i = 0; i < 4; i++) {
        int c = tid + i * 256;
        po[c] = (v[i] - mu) * inv * g[c] + bt[c];
    }
}

// ---------------------------------------------------------------------------
// Host orchestration
// ---------------------------------------------------------------------------
extern "C" void kernel_launch(void* const* d_in, const int* in_sizes, int n_in,
                              void* d_out, int out_size)
{
    const int*   x    = (const int*)  d_in[0];
    const float* emb  = (const float*)d_in[1];
    const float* wq   = (const float*)d_in[2];
    const float* bq   = (const float*)d_in[3];
    const float* wk   = (const float*)d_in[4];
    const float* bk   = (const float*)d_in[5];
    const float* wv   = (const float*)d_in[6];
    const float* bv   = (const float*)d_in[7];
    const float* wr   = (const float*)d_in[8];
    const float* br   = (const float*)d_in[9];
    const float* ln1g = (const float*)d_in[10];
    const float* ln1b = (const float*)d_in[11];
    const float* w1   = (const float*)d_in[12];
    const float* b1   = (const float*)d_in[13];
    const float* w2   = (const float*)d_in[14];
    const float* b2   = (const float*)d_in[15];
    const float* ln2g = (const float*)d_in[16];
    const float* ln2b = (const float*)d_in[17];
    const float* wf   = (const float*)d_in[18];
    const float* bf   = (const float*)d_in[19];
    float* out = (float*)d_out;

    float *pos, *h, *q, *k, *v, *sc, *oc, *a, *fin, *mid;
    cudaGetSymbolAddress((void**)&pos, g_pos);
    cudaGetSymbolAddress((void**)&h,   g_h);
    cudaGetSymbolAddress((void**)&q,   g_q);
    cudaGetSymbolAddress((void**)&k,   g_k);
    cudaGetSymbolAddress((void**)&v,   g_v);
    cudaGetSymbolAddress((void**)&sc,  g_sc);
    cudaGetSymbolAddress((void**)&oc,  g_oc);
    cudaGetSymbolAddress((void**)&a,   g_a);
    cudaGetSymbolAddress((void**)&fin, g_fin);
    cudaGetSymbolAddress((void**)&mid, g_mid);

    freq_kernel<<<2, 256>>>();
    posenc_kernel<<<(Sv * Dv) / 256, 256>>>(pos);
    embed_kernel<<<(BSv * Dv) / 256, 256>>>(x, emb, pos, h);

    const long long HS  = (long long)Sv * QSv;       // per-(b,h) Q/K/V block
    const long long HBS = (long long)BSv * QSv;      // per-head Q/K/V block
    const long long SS  = (long long)Sv * Sv;

    for (int l = 0; l < Lv; l++) {
        const float* wq_l = wq + (size_t)l * Hv * Dv * QSv;
        const float* wk_l = wk + (size_t)l * Hv * Dv * QSv;
        const float* wv_l = wv + (size_t)l * Hv * Dv * QSv;
        const float* bq_l = bq + (size_t)l * Hv * QSv;
        const float* bk_l = bk + (size_t)l * Hv * QSv;
        const float* bv_l = bv + (size_t)l * Hv * QSv;
        const float* wr_l = wr + (size_t)l * HQ * Dv;
        const float* br_l = br + (size_t)l * Dv;
        const float* w1_l = w1 + (size_t)l * Dv * FFv;
        const float* b1_l = b1 + (size_t)l * FFv;
        const float* w2_l = w2 + (size_t)l * FFv * Dv;
        const float* b2_l = b2 + (size_t)l * Dv;

        // Q/K/V projections: per-head GEMM [B*S, D] @ [D, QS], z over heads
        gemm_kernel<false><<<dim3(BSv/128, QSv/128, Hv), 256>>>(
            h, Dv, 0, 0, wq_l, QSv, (long long)Dv*QSv, 0,
            q, QSv, HBS, 0, bq_l, QSv, BSv, QSv, Dv, 1, 0, 0);
        gemm_kernel<false><<<dim3(BSv/128, QSv/128, Hv), 256>>>(
            h, Dv, 0, 0, wk_l, QSv, (long long)Dv*QSv, 0,
            k, QSv, HBS, 0, bk_l, QSv, BSv, QSv, Dv, 1, 0, 0);
        gemm_kernel<false><<<dim3(BSv/128, QSv/128, Hv), 256>>>(
            h, Dv, 0, 0, wv_l, QSv, (long long)Dv*QSv, 0,
            v, QSv, HBS, 0, bv_l, QSv, BSv, QSv, Dv, 1, 0, 0);

        // scores = Q @ K^T per (h,b), z = h*B + b; upper-triangle tiles skipped
        gemm_kernel<true><<<dim3(Sv/128, Sv/128, Hv*Bv), 256>>>(
            q, QSv, HS, 0, k, QSv, HS, 0,
            sc, Sv, SS, 0, nullptr, 0, Sv, Sv, QSv, 1, 0, 1);

        // causal softmax (scale applied inside; masked entries ignore memory)
        softmax_kernel<<<Hv * Bv * Sv, 256>>>(sc);

        // o = attn @ V (K clamped to diagonal), concat layout [B*S, H*QS]
        gemm_kernel<false><<<dim3(Sv/128, QSv/128, Hv*Bv), 256>>>(
            sc, Sv, (long long)Bv*SS, SS,
            v, QSv, HBS, HS,
            oc, HQ, QSv, (long long)Sv*HQ,
            nullptr, 0, Sv, QSv, Sv, Bv, 0, 2);

        // reducing layer: a = o_cat @ wr + br   [4096, 8192] @ [8192, 1024]
        gemm_kernel<false><<<dim3(BSv/128, Dv/128, 1), 256>>>(
            oc, HQ, 0, 0, wr_l, Dv, 0, 0,
            a, Dv, 0, 0, br_l, 0, BSv, Dv, HQ, 1, 0, 0);

        // ff_in = LN(a + h)
        add_ln_kernel<<<BSv, 256>>>(a, h, ln1g + (size_t)l*Dv, ln1b + (size_t)l*Dv, fin);

        // FFN
        gemm_kernel<false><<<dim3(BSv/128, FFv/128, 1), 256>>>(
            fin, Dv, 0, 0, w1_l, FFv, 0, 0,
            mid, FFv, 0, 0, b1_l, 0, BSv, FFv, Dv, 1, 1, 0);
        gemm_kernel<false><<<dim3(BSv/128, Dv/128, 1), 256>>>(
            mid, FFv, 0, 0, w2_l, Dv, 0, 0,
            a, Dv, 0, 0, b2_l, 0, BSv, Dv, FFv, 1, 0, 0);

        // h = LN(ff + ff_in)
        add_ln_kernel<<<BSv, 256>>>(a, fin, ln2g + (size_t)l*Dv, ln2b + (size_t)l*Dv, h);
    }

    // logits = h @ wf + bf   [4096, 1024] @ [1024, 32000]
    gemm_kernel<false><<<dim3(BSv/128, Vv/128, 1), 256>>>(
        h, Dv, 0, 0, wf, Vv, 0, 0,
        out, Vv, 0, 0, bf, 0, BSv, Vv, Dv, 1, 0, 0);
}